// round 1
// baseline (speedup 1.0000x reference)
#include <cuda_runtime.h>
#include <math_constants.h>

// EvalEig: eigenvalues of 16 symmetric tridiagonal matrices (B=4, L=4, N=2000)
//   diag_i = 800 + ptl[b,i] + l(l+1)/r_i^2,  r_i = 0.05*(i+1)
//   offdiag = -400 (constant)  =>  b^2 = 160000
// Method: Sturm-sequence bisection, one thread per eigenvalue index.

#define RN   2000
#define NMAT 16
#define B2   160000.0f
#define TWO_S 800.0f
#define NTHREADS 256

__device__ __forceinline__ float frcp(float x) {
    float r;
    asm("rcp.approx.ftz.f32 %0, %1;" : "=f"(r) : "f"(x));
    return r;
}

// negcount: # of eigenvalues of T strictly below x, via LDL^T Sturm recurrence.
// d_0 = inf so the first step yields d = a_0 - x. IEEE inf arithmetic makes the
// recurrence self-recovering through tiny/zero pivots (no pivmin needed).
__device__ __forceinline__ int sturm_count(const float* __restrict__ sd, float x) {
    float d = CUDART_INF_F;
    int cnt = 0;
#pragma unroll 2
    for (int i = 0; i < RN; i += 4) {
        float4 a4 = *reinterpret_cast<const float4*>(sd + i);
        d = fmaf(-B2, frcp(d), a4.x - x); cnt += (int)(__float_as_uint(d) >> 31);
        d = fmaf(-B2, frcp(d), a4.y - x); cnt += (int)(__float_as_uint(d) >> 31);
        d = fmaf(-B2, frcp(d), a4.z - x); cnt += (int)(__float_as_uint(d) >> 31);
        d = fmaf(-B2, frcp(d), a4.w - x); cnt += (int)(__float_as_uint(d) >> 31);
    }
    return cnt;
}

__global__ __launch_bounds__(NTHREADS, 4)
void eval_eig_kernel(const float* __restrict__ ptl, float* __restrict__ out) {
    __shared__ __align__(16) float sd[RN];
    __shared__ float wmin[NTHREADS / 32], wmax[NTHREADS / 32];
    __shared__ float bounds[2];

    const int mat = blockIdx.y;          // 0..15  -> (b, l)
    const int b   = mat >> 2;
    const int l   = mat & 3;
    const float ll1 = (float)(l * (l + 1));

    // Build diagonal in shared memory + track min/max for Gershgorin bounds.
    float lmin = CUDART_INF_F, lmax = -CUDART_INF_F;
    for (int i = threadIdx.x; i < RN; i += NTHREADS) {
        float r   = 0.05f * (float)(i + 1);
        float dia = TWO_S + ptl[b * RN + i] + ll1 / (r * r);
        sd[i] = dia;
        lmin = fminf(lmin, dia);
        lmax = fmaxf(lmax, dia);
    }
#pragma unroll
    for (int off = 16; off; off >>= 1) {
        lmin = fminf(lmin, __shfl_xor_sync(0xffffffffu, lmin, off));
        lmax = fmaxf(lmax, __shfl_xor_sync(0xffffffffu, lmax, off));
    }
    const int wid = threadIdx.x >> 5;
    if ((threadIdx.x & 31) == 0) { wmin[wid] = lmin; wmax[wid] = lmax; }
    __syncthreads();
    if (threadIdx.x == 0) {
        float a = wmin[0], c = wmax[0];
#pragma unroll
        for (int w = 1; w < NTHREADS / 32; w++) {
            a = fminf(a, wmin[w]);
            c = fmaxf(c, wmax[w]);
        }
        bounds[0] = a - (TWO_S + 1.0f);   // count(lo) == 0
        bounds[1] = c + (TWO_S + 1.0f);   // count(hi) == RN
    }
    __syncthreads();

    float lo = bounds[0], hi = bounds[1];
    const int k  = blockIdx.x * NTHREADS + threadIdx.x;   // eigenvalue index
    const int kk = min(k, RN - 1);  // lanes past RN do dummy work (keeps warp votes sound)

    // Bisection: invariant count(lo) <= kk < count(hi).
#pragma unroll 1
    for (int it = 0; it < 50; it++) {
        float mid = 0.5f * (lo + hi);
        bool stuck = (mid <= lo) || (mid >= hi);   // fp32 interval collapsed to <= 1 ulp
        if (__all_sync(0xffffffffu, stuck)) break;
        int cnt = sturm_count(sd, mid);
        if (cnt <= kk) lo = mid; else hi = mid;
    }

    if (k < RN) out[mat * RN + k] = 0.5f * (lo + hi);
}

extern "C" void kernel_launch(void* const* d_in, const int* in_sizes, int n_in,
                              void* d_out, int out_size) {
    (void)in_sizes; (void)n_in; (void)out_size;
    const float* ptl = (const float*)d_in[0];
    float* out = (float*)d_out;
    dim3 grid((RN + NTHREADS - 1) / NTHREADS, NMAT);   // (8, 16)
    eval_eig_kernel<<<grid, NTHREADS>>>(ptl, out);
}

// round 2
// speedup vs baseline: 3.6366x; 3.6366x over previous
#include <cuda_runtime.h>
#include <math_constants.h>

// EvalEig: eigenvalues of 16 symmetric tridiagonal matrices (B=4, L=4, N=2000)
//   diag_i = 800 + ptl[b,i] + l(l+1)/r_i^2,  offdiag = -400
// Method: Sturm bisection, one thread per eigenvalue, with a DIVISION-FREE
// scaled characteristic-polynomial recurrence:
//   p^_i = (a^_i - x^) p^_{i-1} - p^_{i-2},   a^ = a/400, x^ = x/400
// count(x) = # sign changes in {p^_0..p^_N}. Critical path = 1 FMA (4 cyc).

#define RN       2000
#define NMAT     16
#define NTHREADS 256
#define INV_B    0.0025f   // 1/400 (matrix scaled so offdiag == 1)
#define BSCALE   400.0f
#define NITER    24        // Gershgorin width ~16 (scaled) -> final ~4e-4 (real)

__device__ __forceinline__ void poly_step(float a, float xh, float& pm1, float& pm2, int& cnt) {
    float pn = fmaf(a - xh, pm1, -pm2);
    cnt += (int)((__float_as_uint(pn) ^ __float_as_uint(pm1)) >> 31);
    pm2 = pm1; pm1 = pn;
}

// # eigenvalues (of the scaled matrix) strictly below xh.
__device__ __forceinline__ int sturm_count(const float* __restrict__ sd, float xh) {
    float pm1 = 1.0f, pm2 = 0.0f;
    int cnt = 0;
#pragma unroll 1
    for (int base = 0; base < RN; base += 16) {
#pragma unroll
        for (int j = 0; j < 16; j += 4) {
            float4 a4 = *reinterpret_cast<const float4*>(sd + base + j);
            poly_step(a4.x, xh, pm1, pm2, cnt);
            poly_step(a4.y, xh, pm1, pm2, cnt);
            poly_step(a4.z, xh, pm1, pm2, cnt);
            poly_step(a4.w, xh, pm1, pm2, cnt);
        }
        // Two-sided rescale: |t| <= ~16 per step -> growth <= 16^16 = 2^64 per
        // window; keeping max(|p|) in [2^-32, 2^32] at window boundaries keeps
        // everything inside fp32 range. Scale is positive -> signs preserved.
        float m  = fmaxf(fabsf(pm1), fabsf(pm2));
        float sc = 1.0f;
        sc = (m > 0x1p32f)  ? 0x1p-64f : sc;
        sc = (m < 0x1p-32f) ? 0x1p64f  : sc;
        pm1 *= sc; pm2 *= sc;
    }
    return cnt;
}

__global__ __launch_bounds__(NTHREADS, 4)
void eval_eig_kernel(const float* __restrict__ ptl, float* __restrict__ out) {
    __shared__ __align__(16) float sd[RN];      // scaled diagonal a/400
    __shared__ float wmin[NTHREADS / 32], wmax[NTHREADS / 32];
    __shared__ float bounds[2];

    const int mat = blockIdx.y;                 // 0..15 -> (b, l)
    const int b   = mat >> 2;
    const int l   = mat & 3;
    const float ll1 = (float)(l * (l + 1));

    // Build scaled diagonal in shared memory; track min/max for Gershgorin.
    // r matches jnp.linspace(0.05, 100, 2000): r_i = 0.05 + i*(99.95/1999).
    const float step = 99.95f / 1999.0f;
    float lmin = CUDART_INF_F, lmax = -CUDART_INF_F;
    for (int i = threadIdx.x; i < RN; i += NTHREADS) {
        float r   = 0.05f + step * (float)i;
        float dia = (800.0f + ptl[b * RN + i] + ll1 / (r * r)) * INV_B;
        sd[i] = dia;
        lmin = fminf(lmin, dia);
        lmax = fmaxf(lmax, dia);
    }
#pragma unroll
    for (int off = 16; off; off >>= 1) {
        lmin = fminf(lmin, __shfl_xor_sync(0xffffffffu, lmin, off));
        lmax = fmaxf(lmax, __shfl_xor_sync(0xffffffffu, lmax, off));
    }
    const int wid = threadIdx.x >> 5;
    if ((threadIdx.x & 31) == 0) { wmin[wid] = lmin; wmax[wid] = lmax; }
    __syncthreads();
    if (threadIdx.x == 0) {
        float a = wmin[0], c = wmax[0];
#pragma unroll
        for (int w = 1; w < NTHREADS / 32; w++) {
            a = fminf(a, wmin[w]);
            c = fmaxf(c, wmax[w]);
        }
        bounds[0] = a - 2.001f;   // scaled offdiag row sum = 2
        bounds[1] = c + 2.001f;
    }
    __syncthreads();

    float lo = bounds[0], hi = bounds[1];
    const int k  = blockIdx.x * NTHREADS + threadIdx.x;   // eigenvalue index
    const int kk = min(k, RN - 1);

    // Fixed-count bisection: invariant count(lo) <= kk < count(hi).
#pragma unroll 1
    for (int it = 0; it < NITER; it++) {
        float mid = 0.5f * (lo + hi);
        int cnt = sturm_count(sd, mid);
        if (cnt <= kk) lo = mid; else hi = mid;
    }

    if (k < RN) out[mat * RN + k] = BSCALE * (0.5f * (lo + hi));
}

extern "C" void kernel_launch(void* const* d_in, const int* in_sizes, int n_in,
                              void* d_out, int out_size) {
    (void)in_sizes; (void)n_in; (void)out_size;
    const float* ptl = (const float*)d_in[0];
    float* out = (float*)d_out;
    dim3 grid((RN + NTHREADS - 1) / NTHREADS, NMAT);   // (8, 16)
    eval_eig_kernel<<<grid, NTHREADS>>>(ptl, out);
}

// round 3
// speedup vs baseline: 5.3282x; 1.4651x over previous
#include <cuda_runtime.h>
#include <math_constants.h>

// EvalEig: eigenvalues of 16 symmetric tridiagonal matrices (B=4, L=4, N=2000)
// Method: Sturm trisection. Each thread owns one eigenvalue and evaluates TWO
// Sturm counts per iteration (packed f32x2) -> interval shrinks 3x/iter.
// Recurrence (scaled so offdiag == 1):  p_i = (a_i - x) p_{i-1} - p_{i-2}.
// Sign substitution q_i = eps_i p_i with eps = (+,+,-,-) period 4 gives
//   q_i = fma( sigma_i*(a_i - x), q_{i-1}, q_{i-2} ),  sigma_i = -1 odd i,
// i.e. NO standalone negation. sigma_i*a_i is pre-stored (duplicated) in
// shared; sigma_i*(-x) alternates between +x and -x packed constants.
// Sign changes of p recovered from signs of q via the known parity pattern
// (XOR with 0xAAAA per 16-step window before popc).

#define RN       2000
#define NMAT     16
#define NTHREADS 256
#define BLKS_PER_MAT 8        // 8*256 = 2048 >= 2000
#define INV_B    0.0025f      // 1/400
#define BSCALE   400.0f
#define NITER    10           // 3^10 = 59049 ~ 15.8 bits
#define NWIN     (RN / 16)    // 125 windows of 16 steps

typedef unsigned long long u64;

__device__ __forceinline__ u64 pack2(float x, float y) {
    u64 r; asm("mov.b64 %0, {%1, %2};" : "=l"(r) : "f"(x), "f"(y)); return r;
}
__device__ __forceinline__ u64 add2(u64 a, u64 b) {
    u64 d; asm("add.rn.f32x2 %0, %1, %2;" : "=l"(d) : "l"(a), "l"(b)); return d;
}
__device__ __forceinline__ u64 fma2(u64 a, u64 b, u64 c) {
    u64 d; asm("fma.rn.f32x2 %0, %1, %2, %3;" : "=l"(d) : "l"(a), "l"(b), "l"(c)); return d;
}
__device__ __forceinline__ unsigned lo32(u64 x) { return (unsigned)x; }
__device__ __forceinline__ unsigned hi32(u64 x) { return (unsigned)(x >> 32); }

// Packed Sturm counts at {x1 (lo half), x2 (hi half)}. Returns counts in c1,c2.
__device__ __forceinline__ void sturm2(const float2* __restrict__ sd2,
                                       float x1, float x2, int& c1, int& c2) {
    const u64 pxh = pack2( x1,  x2);   // used on odd polynomial steps (sigma=-1)
    const u64 nxh = pack2(-x1, -x2);   // used on even polynomial steps
    u64 qp = 0;                        // q_{-1} = {0,0}
    u64 qc = pack2(1.0f, 1.0f);        // q_0   = {1,1}
    unsigned mlo = 0, mhi = 0;         // sign masks (bit16 of window = prev sign)
    int clo = 0, chi = 0;

#pragma unroll 1
    for (int w = 0; w < NWIN; w++) {
        const float2* p = sd2 + (w << 4);
#pragma unroll
        for (int j = 0; j < 16; j += 2) {
            const float4 dd = *reinterpret_cast<const float4*>(p + j);
            // array idx even -> poly step i odd: sh=-a, addend +x
            u64 t0 = add2(pack2(dd.x, dd.y), pxh);
            u64 qn = fma2(t0, qc, qp);
            qp = qc; qc = qn;
            mlo = __funnelshift_l(lo32(qc), mlo, 1);
            mhi = __funnelshift_l(hi32(qc), mhi, 1);
            // array idx odd -> poly step i even: sh=+a, addend -x
            u64 t1 = add2(pack2(dd.z, dd.w), nxh);
            qn = fma2(t1, qc, qp);
            qp = qc; qc = qn;
            mlo = __funnelshift_l(lo32(qc), mlo, 1);
            mhi = __funnelshift_l(hi32(qc), mhi, 1);
        }
        // Count sign changes of p in this 16-step window. Bit k of (m^(m>>1))
        // pairs consecutive q-signs; bit16 carries the previous window's last
        // sign. XOR 0xAAAA undoes the eps parity (odd steps flip q vs p sign).
        clo += __popc(((mlo ^ (mlo >> 1)) & 0xFFFFu) ^ 0xAAAAu);
        chi += __popc(((mhi ^ (mhi >> 1)) & 0xFFFFu) ^ 0xAAAAu);
        // Two-sided rescale (positive factors -> signs preserved). Per half.
        {
            float c0 = __uint_as_float(lo32(qc)), p0 = __uint_as_float(lo32(qp));
            float c1f = __uint_as_float(hi32(qc)), p1f = __uint_as_float(hi32(qp));
            float m0 = fmaxf(fabsf(c0), fabsf(p0));
            float m1 = fmaxf(fabsf(c1f), fabsf(p1f));
            float s0 = (m0 > 0x1p32f) ? 0x1p-64f : ((m0 < 0x1p-32f) ? 0x1p64f : 1.0f);
            float s1 = (m1 > 0x1p32f) ? 0x1p-64f : ((m1 < 0x1p-32f) ? 0x1p64f : 1.0f);
            qc = pack2(c0 * s0, c1f * s1);
            qp = pack2(p0 * s0, p1f * s1);
        }
    }
    c1 = clo; c2 = chi;
}

__global__ __launch_bounds__(NTHREADS, 1)
void eval_eig_kernel(const float* __restrict__ ptl, float* __restrict__ out) {
    __shared__ __align__(16) float2 sd2[RN];   // {sigma_i*a_i, same} duplicated
    __shared__ float wmin[NTHREADS / 32], wmax[NTHREADS / 32];
    __shared__ float bounds[2];

    const int mat = blockIdx.y;                // 0..15 -> (b, l)
    const int b   = mat >> 2;
    const int l   = mat & 3;
    const float ll1 = (float)(l * (l + 1));

    // Build signed, duplicated, scaled diagonal; Gershgorin min/max of a.
    const float step = 99.95f / 1999.0f;       // jnp.linspace(0.05, 100, 2000)
    float lmin = CUDART_INF_F, lmax = -CUDART_INF_F;
    for (int i = threadIdx.x; i < RN; i += NTHREADS) {
        float r  = 0.05f + step * (float)i;
        float a  = (800.0f + ptl[b * RN + i] + ll1 / (r * r)) * INV_B;
        float sa = (i & 1) ? a : -a;           // idx even <-> poly step odd -> -a
        sd2[i] = make_float2(sa, sa);
        lmin = fminf(lmin, a);
        lmax = fmaxf(lmax, a);
    }
#pragma unroll
    for (int off = 16; off; off >>= 1) {
        lmin = fminf(lmin, __shfl_xor_sync(0xffffffffu, lmin, off));
        lmax = fmaxf(lmax, __shfl_xor_sync(0xffffffffu, lmax, off));
    }
    const int wid = threadIdx.x >> 5;
    if ((threadIdx.x & 31) == 0) { wmin[wid] = lmin; wmax[wid] = lmax; }
    __syncthreads();
    if (threadIdx.x == 0) {
        float a = wmin[0], c = wmax[0];
#pragma unroll
        for (int w = 1; w < NTHREADS / 32; w++) {
            a = fminf(a, wmin[w]);
            c = fmaxf(c, wmax[w]);
        }
        bounds[0] = a - 2.001f;    // scaled offdiag row sum = 2
        bounds[1] = c + 2.001f;
    }
    __syncthreads();

    float lo = bounds[0], hi = bounds[1];
    const int k  = blockIdx.x * NTHREADS + threadIdx.x;   // eigenvalue index
    const int kk = min(k, RN - 1);

    // Trisection: invariant count(lo) <= kk < count(hi); width /3 per iter.
#pragma unroll 1
    for (int it = 0; it < NITER; it++) {
        float w3 = (hi - lo) * (1.0f / 3.0f);
        float x1 = lo + w3;
        float x2 = hi - w3;
        int c1, c2;
        sturm2(sd2, x1, x2, c1, c2);
        if (c1 > kk)       hi = x1;
        else if (c2 > kk) { lo = x1; hi = x2; }
        else               lo = x2;
    }

    if (k < RN) out[mat * RN + k] = BSCALE * (0.5f * (lo + hi));
}

extern "C" void kernel_launch(void* const* d_in, const int* in_sizes, int n_in,
                              void* d_out, int out_size) {
    (void)in_sizes; (void)n_in; (void)out_size;
    const float* ptl = (const float*)d_in[0];
    float* out = (float*)d_out;
    dim3 grid(BLKS_PER_MAT, NMAT);   // (8, 16) = 128 blocks
    eval_eig_kernel<<<grid, NTHREADS>>>(ptl, out);
}

// round 5
// speedup vs baseline: 7.8110x; 1.4660x over previous
#include <cuda_runtime.h>
#include <math_constants.h>

// EvalEig: eigenvalues of 16 symmetric tridiagonal matrices (B=4, L=4, N=2000)
// Sturm trisection, one thread per eigenvalue, TWO packed f32x2 Sturm counts
// per iteration -> interval/3 per round. Division-free recurrence
//   q_i = fma( sigma_i*(a_i - x), q_{i-1}, q_{i-2} ),  sigma_i = -1 for odd i.
// sigma_i*a_i stored PRE-PACKED as u64 {sa,sa} in shared (LDS.128 -> add2
// directly). Sign changes of p counted per 32-step window via popc; q is
// RESCALED every 16 steps (band [2^-32, 2^32]; worst per-16-step growth is
// ~2^63, so |q| stays < 2^96 -- the 32-step rescale of the previous round
// overflowed to inf and corrupted counts).

#define RN       2000
#define NMAT     16
#define NTHREADS 256
#define BLKS_PER_MAT 8        // 8*256 = 2048 >= 2000
#define INV_B    0.0025f      // 1/400 (offdiag scaled to 1)
#define BSCALE   400.0f
#define NITER    8            // 3^8 = 6561 -> rel_err ~1.8e-4 (threshold 1e-3)
#define NWIN32   62           // 62*32 = 1984 steps, + 16-step tail

typedef unsigned long long u64;

__device__ __forceinline__ u64 pack2(float x, float y) {
    u64 r; asm("mov.b64 %0, {%1, %2};" : "=l"(r) : "f"(x), "f"(y)); return r;
}
__device__ __forceinline__ u64 add2(u64 a, u64 b) {
    u64 d; asm("add.rn.f32x2 %0, %1, %2;" : "=l"(d) : "l"(a), "l"(b)); return d;
}
__device__ __forceinline__ u64 fma2(u64 a, u64 b, u64 c) {
    u64 d; asm("fma.rn.f32x2 %0, %1, %2, %3;" : "=l"(d) : "l"(a), "l"(b), "l"(c)); return d;
}
__device__ __forceinline__ unsigned lo32(u64 x) { return (unsigned)x; }
__device__ __forceinline__ unsigned hi32(u64 x) { return (unsigned)(x >> 32); }

// One recurrence step: v = {sa,sa}; xh = {±x1, ±x2} per index parity.
#define STEP(v, xh)                                             \
    do {                                                        \
        u64 qn = fma2(add2((v), (xh)), qc, qp);                 \
        qp = qc; qc = qn;                                       \
        mlo = __funnelshift_l(lo32(qc), mlo, 1);                \
        mhi = __funnelshift_l(hi32(qc), mhi, 1);                \
    } while (0)

// Two-sided rescale into [2^-32, 2^32] (positive factors preserve signs).
#define RESCALE()                                                              \
    do {                                                                       \
        float c0 = __uint_as_float(lo32(qc)), p0 = __uint_as_float(lo32(qp));  \
        float c1f = __uint_as_float(hi32(qc)), p1f = __uint_as_float(hi32(qp));\
        float m0 = fmaxf(fabsf(c0), fabsf(p0));                                \
        float m1 = fmaxf(fabsf(c1f), fabsf(p1f));                              \
        float s0 = (m0 > 0x1p32f) ? 0x1p-64f : ((m0 < 0x1p-32f) ? 0x1p64f : 1.0f); \
        float s1 = (m1 > 0x1p32f) ? 0x1p-64f : ((m1 < 0x1p-32f) ? 0x1p64f : 1.0f); \
        qc = pack2(c0 * s0, c1f * s1);                                         \
        qp = pack2(p0 * s0, p1f * s1);                                         \
    } while (0)

// Packed Sturm counts at {x1 (lo), x2 (hi)}.
__device__ __forceinline__ void sturm2(const u64* __restrict__ sdp,
                                       float x1, float x2, int& c1, int& c2) {
    const u64 pxh = pack2( x1,  x2);   // array idx even (poly step odd, sigma=-1)
    const u64 nxh = pack2(-x1, -x2);   // array idx odd
    u64 qp = 0;                        // q_{-1}
    u64 qc = pack2(1.0f, 1.0f);        // q_0 (sign +, matches initial mask=0)
    unsigned mlo = 0, mhi = 0;
    int clo = 0, chi = 0;

#pragma unroll 1
    for (int w = 0; w < NWIN32; w++) {
        const ulonglong2* p = reinterpret_cast<const ulonglong2*>(sdp + (w << 5));
        const unsigned plo = mlo, phi = mhi;   // carry last sign of prev window
#pragma unroll
        for (int h = 0; h < 2; h++) {          // two 16-step halves
#pragma unroll
            for (int j = 0; j < 8; j++) {
                ulonglong2 vv = p[h * 8 + j];
                STEP(vv.x, pxh);
                STEP(vv.y, nxh);
            }
            RESCALE();                         // every 16 steps (safe band)
        }
        clo += __popc((mlo ^ ((mlo >> 1) | (plo << 31))) ^ 0xAAAAAAAAu);
        chi += __popc((mhi ^ ((mhi >> 1) | (phi << 31))) ^ 0xAAAAAAAAu);
    }
    // 16-step tail (steps 1985..2000); bit16 of rolling mask = prev sign.
    {
        const ulonglong2* p = reinterpret_cast<const ulonglong2*>(sdp + (NWIN32 << 5));
#pragma unroll
        for (int j = 0; j < 8; j++) {
            ulonglong2 vv = p[j];
            STEP(vv.x, pxh);
            STEP(vv.y, nxh);
        }
        clo += __popc(((mlo ^ (mlo >> 1)) & 0xFFFFu) ^ 0xAAAAu);
        chi += __popc(((mhi ^ (mhi >> 1)) & 0xFFFFu) ^ 0xAAAAu);
    }
    c1 = clo; c2 = chi;
}

__global__ __launch_bounds__(NTHREADS, 1)
void eval_eig_kernel(const float* __restrict__ ptl, float* __restrict__ out) {
    __shared__ __align__(16) u64 sdp[RN];      // {sigma_i*a_i, same} packed
    __shared__ float wmin[NTHREADS / 32], wmax[NTHREADS / 32];
    __shared__ float bounds[2];

    const int mat = blockIdx.y;                // 0..15 -> (b, l)
    const int b   = mat >> 2;
    const int l   = mat & 3;
    const float ll1 = (float)(l * (l + 1));

    // Scaled, signed, duplicated diagonal; Gershgorin min/max of a.
    const float step = 99.95f / 1999.0f;       // jnp.linspace(0.05, 100, 2000)
    float lmin = CUDART_INF_F, lmax = -CUDART_INF_F;
    for (int i = threadIdx.x; i < RN; i += NTHREADS) {
        float r  = 0.05f + step * (float)i;
        float a  = (800.0f + ptl[b * RN + i] + ll1 / (r * r)) * INV_B;
        float sa = (i & 1) ? a : -a;           // idx even <-> poly step odd -> -a
        sdp[i] = pack2(sa, sa);
        lmin = fminf(lmin, a);
        lmax = fmaxf(lmax, a);
    }
#pragma unroll
    for (int off = 16; off; off >>= 1) {
        lmin = fminf(lmin, __shfl_xor_sync(0xffffffffu, lmin, off));
        lmax = fmaxf(lmax, __shfl_xor_sync(0xffffffffu, lmax, off));
    }
    const int wid = threadIdx.x >> 5;
    if ((threadIdx.x & 31) == 0) { wmin[wid] = lmin; wmax[wid] = lmax; }
    __syncthreads();
    if (threadIdx.x == 0) {
        float a = wmin[0], c = wmax[0];
#pragma unroll
        for (int w = 1; w < NTHREADS / 32; w++) {
            a = fminf(a, wmin[w]);
            c = fmaxf(c, wmax[w]);
        }
        bounds[0] = a - 2.001f;    // scaled offdiag row sum = 2
        bounds[1] = c + 2.001f;
    }
    __syncthreads();

    float lo = bounds[0], hi = bounds[1];
    const int k  = blockIdx.x * NTHREADS + threadIdx.x;
    const int kk = min(k, RN - 1);

#pragma unroll 1
    for (int it = 0; it < NITER; it++) {
        float w3 = (hi - lo) * (1.0f / 3.0f);
        float x1 = lo + w3;
        float x2 = hi - w3;
        int c1, c2;
        sturm2(sdp, x1, x2, c1, c2);
        if (c1 > kk)       hi = x1;
        else if (c2 > kk) { lo = x1; hi = x2; }
        else               lo = x2;
    }

    if (k < RN) out[mat * RN + k] = BSCALE * (0.5f * (lo + hi));
}

extern "C" void kernel_launch(void* const* d_in, const int* in_sizes, int n_in,
                              void* d_out, int out_size) {
    (void)in_sizes; (void)n_in; (void)out_size;
    const float* ptl = (const float*)d_in[0];
    float* out = (float*)d_out;
    dim3 grid(BLKS_PER_MAT, NMAT);   // (8, 16) = 128 blocks
    eval_eig_kernel<<<grid, NTHREADS>>>(ptl, out);
}

// round 6
// speedup vs baseline: 13.8674x; 1.7754x over previous
#include <cuda_runtime.h>
#include <math_constants.h>

// EvalEig: eigenvalues of 16 symmetric tridiagonal matrices (B=4, L=4, N=2000)
// Two-phase Sturm method, one thread per eigenvalue:
//   Phase 1 (cooperative): block evaluates Sturm counts at 512 grid points
//     spanning the Gershgorin interval (2 probes/thread = ONE packed sweep);
//     the shared count table gives every eigenvalue a width-W/512 bracket.
//   Phase 2: 3 packed-trisection rounds -> final width W/512/27.
// Recurrence (scaled, offdiag=1):  q_i = fma(sigma_i*(a_i-x), q_{i-1}, q_{i-2}),
// sigma_i = -1 odd i (sign substitution, no negation op). sigma_i*a_i stored
// PRE-PACKED as u64 {sa,sa} in shared. Signs counted per 32-step window via
// popc; q rescaled every 16 steps (band [2^-32,2^32] -- proven safe in R5).

#define RN       2000
#define NMAT     16
#define NTHREADS 256
#define BLKS_PER_MAT 8        // 8*256 = 2048 >= 2000
#define INV_B    0.0025f      // 1/400 (offdiag scaled to 1)
#define BSCALE   400.0f
#define NGRID    512
#define NITER    3            // trisection rounds after grid bracket
#define NWIN32   62           // 62*32 = 1984 steps, + 16-step tail

typedef unsigned long long u64;

__device__ __forceinline__ u64 pack2(float x, float y) {
    u64 r; asm("mov.b64 %0, {%1, %2};" : "=l"(r) : "f"(x), "f"(y)); return r;
}
__device__ __forceinline__ u64 add2(u64 a, u64 b) {
    u64 d; asm("add.rn.f32x2 %0, %1, %2;" : "=l"(d) : "l"(a), "l"(b)); return d;
}
__device__ __forceinline__ u64 fma2(u64 a, u64 b, u64 c) {
    u64 d; asm("fma.rn.f32x2 %0, %1, %2, %3;" : "=l"(d) : "l"(a), "l"(b), "l"(c)); return d;
}
__device__ __forceinline__ unsigned lo32(u64 x) { return (unsigned)x; }
__device__ __forceinline__ unsigned hi32(u64 x) { return (unsigned)(x >> 32); }

#define STEP(v, xh)                                             \
    do {                                                        \
        u64 qn = fma2(add2((v), (xh)), qc, qp);                 \
        qp = qc; qc = qn;                                       \
        mlo = __funnelshift_l(lo32(qc), mlo, 1);                \
        mhi = __funnelshift_l(hi32(qc), mhi, 1);                \
    } while (0)

#define RESCALE()                                                              \
    do {                                                                       \
        float c0 = __uint_as_float(lo32(qc)), p0 = __uint_as_float(lo32(qp));  \
        float c1f = __uint_as_float(hi32(qc)), p1f = __uint_as_float(hi32(qp));\
        float m0 = fmaxf(fabsf(c0), fabsf(p0));                                \
        float m1 = fmaxf(fabsf(c1f), fabsf(p1f));                              \
        float s0 = (m0 > 0x1p32f) ? 0x1p-64f : ((m0 < 0x1p-32f) ? 0x1p64f : 1.0f); \
        float s1 = (m1 > 0x1p32f) ? 0x1p-64f : ((m1 < 0x1p-32f) ? 0x1p64f : 1.0f); \
        qc = pack2(c0 * s0, c1f * s1);                                         \
        qp = pack2(p0 * s0, p1f * s1);                                         \
    } while (0)

// Packed Sturm counts at {x1 (lo), x2 (hi)}.
__device__ __forceinline__ void sturm2(const u64* __restrict__ sdp,
                                       float x1, float x2, int& c1, int& c2) {
    const u64 pxh = pack2( x1,  x2);   // array idx even (poly step odd, sigma=-1)
    const u64 nxh = pack2(-x1, -x2);   // array idx odd
    u64 qp = 0;
    u64 qc = pack2(1.0f, 1.0f);
    unsigned mlo = 0, mhi = 0;
    int clo = 0, chi = 0;

#pragma unroll 1
    for (int w = 0; w < NWIN32; w++) {
        const ulonglong2* p = reinterpret_cast<const ulonglong2*>(sdp + (w << 5));
        const unsigned plo = mlo, phi = mhi;
#pragma unroll
        for (int h = 0; h < 2; h++) {
#pragma unroll
            for (int j = 0; j < 8; j++) {
                ulonglong2 vv = p[h * 8 + j];
                STEP(vv.x, pxh);
                STEP(vv.y, nxh);
            }
            RESCALE();
        }
        clo += __popc((mlo ^ ((mlo >> 1) | (plo << 31))) ^ 0xAAAAAAAAu);
        chi += __popc((mhi ^ ((mhi >> 1) | (phi << 31))) ^ 0xAAAAAAAAu);
    }
    {   // 16-step tail (steps 1985..2000)
        const ulonglong2* p = reinterpret_cast<const ulonglong2*>(sdp + (NWIN32 << 5));
#pragma unroll
        for (int j = 0; j < 8; j++) {
            ulonglong2 vv = p[j];
            STEP(vv.x, pxh);
            STEP(vv.y, nxh);
        }
        clo += __popc(((mlo ^ (mlo >> 1)) & 0xFFFFu) ^ 0xAAAAu);
        chi += __popc(((mhi ^ (mhi >> 1)) & 0xFFFFu) ^ 0xAAAAu);
    }
    c1 = clo; c2 = chi;
}

__global__ __launch_bounds__(NTHREADS, 1)
void eval_eig_kernel(const float* __restrict__ ptl, float* __restrict__ out) {
    __shared__ __align__(16) u64 sdp[RN];      // {sigma_i*a_i, same} packed
    __shared__ int   ctab[NGRID + 1];          // Sturm counts at grid points
    __shared__ float wmin[NTHREADS / 32], wmax[NTHREADS / 32];
    __shared__ float bounds[2];

    const int mat = blockIdx.y;                // 0..15 -> (b, l)
    const int b   = mat >> 2;
    const int l   = mat & 3;
    const float ll1 = (float)(l * (l + 1));
    const int t   = threadIdx.x;

    // Scaled, signed, duplicated diagonal; Gershgorin min/max of a.
    const float step = 99.95f / 1999.0f;       // jnp.linspace(0.05, 100, 2000)
    float lmin = CUDART_INF_F, lmax = -CUDART_INF_F;
    for (int i = t; i < RN; i += NTHREADS) {
        float r  = 0.05f + step * (float)i;
        float a  = (800.0f + ptl[b * RN + i] + ll1 / (r * r)) * INV_B;
        float sa = (i & 1) ? a : -a;
        sdp[i] = pack2(sa, sa);
        lmin = fminf(lmin, a);
        lmax = fmaxf(lmax, a);
    }
#pragma unroll
    for (int off = 16; off; off >>= 1) {
        lmin = fminf(lmin, __shfl_xor_sync(0xffffffffu, lmin, off));
        lmax = fmaxf(lmax, __shfl_xor_sync(0xffffffffu, lmax, off));
    }
    const int wid = t >> 5;
    if ((t & 31) == 0) { wmin[wid] = lmin; wmax[wid] = lmax; }
    __syncthreads();
    if (t == 0) {
        float a = wmin[0], c = wmax[0];
#pragma unroll
        for (int w = 1; w < NTHREADS / 32; w++) {
            a = fminf(a, wmin[w]);
            c = fmaxf(c, wmax[w]);
        }
        bounds[0] = a - 2.001f;    // scaled offdiag row sum = 2
        bounds[1] = c + 2.001f;
    }
    __syncthreads();

    const float b0 = bounds[0];
    const float gw = (bounds[1] - bounds[0]) * (1.0f / (float)NGRID);

    // ---- Phase 1: cooperative grid (512 probes, 2 per thread, ONE sweep) ----
    {
        float gx1 = b0 + gw * (float)(2 * t + 1);
        float gx2 = b0 + gw * (float)(2 * t + 2);
        int c1, c2;
        sturm2(sdp, gx1, gx2, c1, c2);
        ctab[2 * t + 1] = c1;
        ctab[2 * t + 2] = c2;
    }
    __syncthreads();
    if (t == 0) { ctab[0] = 0; ctab[NGRID] = RN; }
    __syncthreads();
    // One monotone relaxation pass (insurance against ulp-level count flips).
    {
        int v1 = max(ctab[t], ctab[t + 1]);
        int v2 = max(ctab[t + 256], ctab[t + 257]);
        __syncthreads();
        ctab[t + 1] = v1;
        ctab[t + 257] = v2;
    }
    __syncthreads();

    // ---- Phase 2: bracket lookup + 3 trisection rounds ----
    const int k  = blockIdx.x * NTHREADS + t;
    const int kk = min(k, RN - 1);

    int jlo = 0, jhi = NGRID;      // invariant: ctab[jlo] <= kk < ctab[jhi]
#pragma unroll
    for (int s = 0; s < 9; s++) {
        int jm = (jlo + jhi) >> 1;
        if (ctab[jm] <= kk) jlo = jm; else jhi = jm;
    }
    float lo = b0 + gw * (float)jlo;
    float hi = b0 + gw * (float)jhi;

#pragma unroll 1
    for (int it = 0; it < NITER; it++) {
        float w3 = (hi - lo) * (1.0f / 3.0f);
        float x1 = lo + w3;
        float x2 = hi - w3;
        int c1, c2;
        sturm2(sdp, x1, x2, c1, c2);
        if (c1 > kk)       hi = x1;
        else if (c2 > kk) { lo = x1; hi = x2; }
        else               lo = x2;
    }

    if (k < RN) out[mat * RN + k] = BSCALE * (0.5f * (lo + hi));
}

extern "C" void kernel_launch(void* const* d_in, const int* in_sizes, int n_in,
                              void* d_out, int out_size) {
    (void)in_sizes; (void)n_in; (void)out_size;
    const float* ptl = (const float*)d_in[0];
    float* out = (float*)d_out;
    dim3 grid(BLKS_PER_MAT, NMAT);   // (8, 16) = 128 blocks
    eval_eig_kernel<<<grid, NTHREADS>>>(ptl, out);
}

// round 7
// speedup vs baseline: 19.5566x; 1.4103x over previous
#include <cuda_runtime.h>
#include <math_constants.h>

// EvalEig: eigenvalues of 16 symmetric tridiagonal matrices (B=4, L=4, N=2000)
// Two-phase Sturm method, one thread per eigenvalue:
//   Phase 1 (cooperative): 512 grid probes per block (2/thread = ONE packed
//     sweep) on a SPLIT grid: 448 fine points over the bulk band
//     [b0, b0+4.85] (scaled), 64 coarse above -> per-eigenvalue bracket.
//   Phase 2: 2 packed-trisection rounds.
// Recurrence (scaled, offdiag=1): q_i = fma(sigma_i*(a_i-x), q_{i-1}, q_{i-2}),
// sigma_i=-1 odd i. sigma_i*a_i pre-packed as u64 {sa,sa} in shared. Signs
// counted per 32 steps via popc; q rescaled every 16 steps with the exponent
// hack s = 2^-ilogb(qc) (AND+ISUB+2 MUL). Tiles of 16 steps are ping-pong
// prefetched into registers so LDS latency hides under compute.

#define RN       2000
#define NMAT     16
#define NTHREADS 256
#define BLKS_PER_MAT 8        // 8*256 = 2048 >= 2000
#define INV_B    0.0025f      // 1/400 (offdiag scaled to 1)
#define BSCALE   400.0f
#define NGRID    512
#define NFINE    448
#define FINE_W   4.85f        // scaled width of fine region
#define NITER    2
#define NHALF    125          // 125 * 16 = 2000 steps

typedef unsigned long long u64;

__device__ __forceinline__ u64 pack2(float x, float y) {
    u64 r; asm("mov.b64 %0, {%1, %2};" : "=l"(r) : "f"(x), "f"(y)); return r;
}
__device__ __forceinline__ u64 add2(u64 a, u64 b) {
    u64 d; asm("add.rn.f32x2 %0, %1, %2;" : "=l"(d) : "l"(a), "l"(b)); return d;
}
__device__ __forceinline__ u64 fma2(u64 a, u64 b, u64 c) {
    u64 d; asm("fma.rn.f32x2 %0, %1, %2, %3;" : "=l"(d) : "l"(a), "l"(b), "l"(c)); return d;
}
__device__ __forceinline__ unsigned lo32(u64 x) { return (unsigned)x; }
__device__ __forceinline__ unsigned hi32(u64 x) { return (unsigned)(x >> 32); }

struct Tile { ulonglong2 v[8]; };   // 16 steps worth of {sa,sa}

__device__ __forceinline__ void load_tile(Tile& t, const ulonglong2* __restrict__ p) {
#pragma unroll
    for (int j = 0; j < 8; j++) t.v[j] = p[j];
}

// 16 recurrence steps from a register tile, then exponent-hack rescale.
__device__ __forceinline__ void do16(const Tile& t, u64 pxh, u64 nxh,
                                     u64& qc, u64& qp,
                                     unsigned& mlo, unsigned& mhi) {
#pragma unroll
    for (int j = 0; j < 8; j++) {
        u64 qn = fma2(add2(t.v[j].x, pxh), qc, qp);      // even idx -> +x
        qp = qc; qc = qn;
        mlo = __funnelshift_l(lo32(qc), mlo, 1);
        mhi = __funnelshift_l(hi32(qc), mhi, 1);
        qn = fma2(add2(t.v[j].y, nxh), qc, qp);          // odd idx -> -x
        qp = qc; qc = qn;
        mlo = __funnelshift_l(lo32(qc), mlo, 1);
        mhi = __funnelshift_l(hi32(qc), mhi, 1);
    }
    // Rescale: s = 2^(-ilogb(qc)) per half; growth <= 2^63/window keeps the
    // exponent field < 0xFE so s > 0 (sign-preserving) always.
    unsigned eb0 = lo32(qc) & 0x7F800000u;
    unsigned eb1 = hi32(qc) & 0x7F800000u;
    float s0 = __uint_as_float(0x7F000000u - eb0);
    float s1 = __uint_as_float(0x7F000000u - eb1);
    qc = pack2(__uint_as_float(lo32(qc)) * s0, __uint_as_float(hi32(qc)) * s1);
    qp = pack2(__uint_as_float(lo32(qp)) * s0, __uint_as_float(hi32(qp)) * s1);
}

// Packed Sturm counts at {x1 (lo), x2 (hi)}; ping-pong prefetched tiles.
__device__ __forceinline__ void sturm2(const u64* __restrict__ sdp,
                                       float x1, float x2, int& c1, int& c2) {
    const u64 pxh = pack2( x1,  x2);
    const u64 nxh = pack2(-x1, -x2);
    const ulonglong2* __restrict__ p = reinterpret_cast<const ulonglong2*>(sdp);
    u64 qp = 0;
    u64 qc = pack2(1.0f, 1.0f);
    unsigned mlo = 0, mhi = 0;
    int clo = 0, chi = 0;

    Tile A, B;
    load_tile(A, p);                      // half 0
#pragma unroll 1
    for (int w = 0; w < 62; w++) {        // halves 2w, 2w+1; preload 2w+2
        const unsigned plo = mlo, phi = mhi;
        load_tile(B, p + (2 * w + 1) * 8);
        do16(A, pxh, nxh, qc, qp, mlo, mhi);
        load_tile(A, p + (2 * w + 2) * 8);   // 2w+2 <= 124: in bounds
        do16(B, pxh, nxh, qc, qp, mlo, mhi);
        clo += __popc((mlo ^ ((mlo >> 1) | (plo << 31))) ^ 0xAAAAAAAAu);
        chi += __popc((mhi ^ ((mhi >> 1) | (phi << 31))) ^ 0xAAAAAAAAu);
    }
    // Tail: half 124 (already in A). Bit16 of rolling mask = previous sign.
    do16(A, pxh, nxh, qc, qp, mlo, mhi);
    clo += __popc(((mlo ^ (mlo >> 1)) & 0xFFFFu) ^ 0xAAAAu);
    chi += __popc(((mhi ^ (mhi >> 1)) & 0xFFFFu) ^ 0xAAAAu);
    c1 = clo; c2 = chi;
}

__global__ __launch_bounds__(NTHREADS, 1)
void eval_eig_kernel(const float* __restrict__ ptl, float* __restrict__ out) {
    __shared__ __align__(16) u64 sdp[RN];      // {sigma_i*a_i, same} packed
    __shared__ int   ctab[NGRID + 1];
    __shared__ float wmin[NTHREADS / 32], wmax[NTHREADS / 32];
    __shared__ float bounds[2];

    const int mat = blockIdx.y;                // 0..15 -> (b, l)
    const int b   = mat >> 2;
    const int l   = mat & 3;
    const float ll1 = (float)(l * (l + 1));
    const int t   = threadIdx.x;

    // Scaled, signed, duplicated diagonal; Gershgorin min/max of a.
    const float step = 99.95f / 1999.0f;       // jnp.linspace(0.05, 100, 2000)
    float lmin = CUDART_INF_F, lmax = -CUDART_INF_F;
    for (int i = t; i < RN; i += NTHREADS) {
        float r  = 0.05f + step * (float)i;
        float a  = (800.0f + ptl[b * RN + i] + ll1 / (r * r)) * INV_B;
        float sa = (i & 1) ? a : -a;
        sdp[i] = pack2(sa, sa);
        lmin = fminf(lmin, a);
        lmax = fmaxf(lmax, a);
    }
#pragma unroll
    for (int off = 16; off; off >>= 1) {
        lmin = fminf(lmin, __shfl_xor_sync(0xffffffffu, lmin, off));
        lmax = fmaxf(lmax, __shfl_xor_sync(0xffffffffu, lmax, off));
    }
    const int wid = t >> 5;
    if ((t & 31) == 0) { wmin[wid] = lmin; wmax[wid] = lmax; }
    __syncthreads();
    if (t == 0) {
        float a = wmin[0], c = wmax[0];
#pragma unroll
        for (int w = 1; w < NTHREADS / 32; w++) {
            a = fminf(a, wmin[w]);
            c = fmaxf(c, wmax[w]);
        }
        bounds[0] = a - 2.001f;    // scaled offdiag row sum = 2
        bounds[1] = c + 2.001f;
    }
    __syncthreads();

    const float b0 = bounds[0];
    const float b1 = bounds[1];
    const float cs = fminf(b0 + FINE_W, b1);            // fine/coarse split
    const float gwf = (cs - b0) * (1.0f / (float)NFINE);
    const float gwc = (b1 - cs) * (1.0f / (float)(NGRID - NFINE));

    // x(j) on the split grid.
    auto gridx = [&](int j) -> float {
        return (j <= NFINE) ? b0 + gwf * (float)j
                            : cs + gwc * (float)(j - NFINE);
    };

    // ---- Phase 1: cooperative split grid (512 probes, ONE sweep) ----
    {
        int c1, c2;
        sturm2(sdp, gridx(2 * t + 1), gridx(2 * t + 2), c1, c2);
        ctab[2 * t + 1] = c1;
        ctab[2 * t + 2] = c2;
    }
    __syncthreads();
    if (t == 0) { ctab[0] = 0; ctab[NGRID] = RN; }
    __syncthreads();
    {   // one monotone relaxation pass (ulp-flip insurance)
        int v1 = max(ctab[t], ctab[t + 1]);
        int v2 = max(ctab[t + 256], ctab[t + 257]);
        __syncthreads();
        ctab[t + 1] = v1;
        ctab[t + 257] = v2;
    }
    __syncthreads();

    // ---- Phase 2: bracket lookup + 2 trisection rounds ----
    const int k  = blockIdx.x * NTHREADS + t;
    const int kk = min(k, RN - 1);

    int jlo = 0, jhi = NGRID;      // invariant: ctab[jlo] <= kk < ctab[jhi]
#pragma unroll
    for (int s = 0; s < 9; s++) {
        int jm = (jlo + jhi) >> 1;
        if (ctab[jm] <= kk) jlo = jm; else jhi = jm;
    }
    float lo = gridx(jlo);
    float hi = gridx(jhi);

#pragma unroll 1
    for (int it = 0; it < NITER; it++) {
        float w3 = (hi - lo) * (1.0f / 3.0f);
        float x1 = lo + w3;
        float x2 = hi - w3;
        int c1, c2;
        sturm2(sdp, x1, x2, c1, c2);
        if (c1 > kk)       hi = x1;
        else if (c2 > kk) { lo = x1; hi = x2; }
        else               lo = x2;
    }

    if (k < RN) out[mat * RN + k] = BSCALE * (0.5f * (lo + hi));
}

extern "C" void kernel_launch(void* const* d_in, const int* in_sizes, int n_in,
                              void* d_out, int out_size) {
    (void)in_sizes; (void)n_in; (void)out_size;
    const float* ptl = (const float*)d_in[0];
    float* out = (float*)d_out;
    dim3 grid(BLKS_PER_MAT, NMAT);   // (8, 16) = 128 blocks
    eval_eig_kernel<<<grid, NTHREADS>>>(ptl, out);
}